// round 1
// baseline (speedup 1.0000x reference)
#include <cuda_runtime.h>
#include <math.h>

#define N 8192
#define C 256

// ---------------- scratch (device globals; no allocation allowed) ----------
__device__ float g_v1n[N * C];
__device__ float g_v2n[N * C];
__device__ float g_p1n[N * C];
__device__ float g_p2n[N * C];
__device__ float g_diag1[N];   // v1n[i] . p2n[i]  (== diag of s1, and p2.v1 loss term)
__device__ float g_diag2[N];   // v2n[i] . p1n[i]  (== diag of s2, and p1.v2 loss term)
__device__ int   g_cnt1[N];    // pos1[i] = # { j != i : s1[i][j] > s1[i][i] }
__device__ int   g_cnt2[N];

// ---------------- block reduce (256 threads) --------------------------------
__device__ __forceinline__ float blockReduceSum256(float v, float* sred) {
    #pragma unroll
    for (int o = 16; o; o >>= 1) v += __shfl_xor_sync(0xffffffffu, v, o);
    int lane = threadIdx.x & 31, w = threadIdx.x >> 5;
    if (lane == 0) sred[w] = v;
    __syncthreads();
    if (w == 0) {
        v = (lane < 8) ? sred[lane] : 0.0f;
        #pragma unroll
        for (int o = 4; o; o >>= 1) v += __shfl_xor_sync(0xffffffffu, v, o);
        if (lane == 0) sred[0] = v;
    }
    __syncthreads();
    float r = sred[0];
    __syncthreads();   // safe reuse of sred
    return r;
}

// ---------------- kernel 1: normalize + diagonal dots -----------------------
__global__ __launch_bounds__(256) void normalize_kernel(
    const float* __restrict__ v1, const float* __restrict__ v2,
    const float* __restrict__ p1, const float* __restrict__ p2)
{
    __shared__ float sred[8];
    int row = blockIdx.x;
    int t = threadIdx.x;
    long off = (long)row * C + t;

    float a = v1[off], b = v2[off], c = p1[off], d = p2[off];

    float na = blockReduceSum256(a * a, sred);
    float nb = blockReduceSum256(b * b, sred);
    float nc = blockReduceSum256(c * c, sred);
    float nd = blockReduceSum256(d * d, sred);

    // x / max(||x||, eps), matching F.normalize semantics
    float ia = 1.0f / fmaxf(sqrtf(na), 1e-12f);
    float ib = 1.0f / fmaxf(sqrtf(nb), 1e-12f);
    float ic = 1.0f / fmaxf(sqrtf(nc), 1e-12f);
    float id = 1.0f / fmaxf(sqrtf(nd), 1e-12f);

    float an = a * ia, bn = b * ib, cn = c * ic, dn = d * id;
    g_v1n[off] = an; g_v2n[off] = bn; g_p1n[off] = cn; g_p2n[off] = dn;

    float d1 = blockReduceSum256(an * dn, sred);   // v1n . p2n
    float d2 = blockReduceSum256(bn * cn, sred);   // v2n . p1n

    if (t == 0) {
        g_diag1[row] = d1;
        g_diag2[row] = d2;
        g_cnt1[row] = 0;
        g_cnt2[row] = 0;
    }
}

// ---------------- kernel 2: fused GEMM + greater-than-diagonal count --------
// Tile: 128x128, K=256 in BK=8 steps, 256 threads, 8x8 microtile per thread.
__global__ __launch_bounds__(256, 2) void count_kernel()
{
    const float* __restrict__ A;
    const float* __restrict__ B;
    const float* __restrict__ diag;
    int* cnt;
    if (blockIdx.z == 0) { A = g_v1n; B = g_p2n; diag = g_diag1; cnt = g_cnt1; }
    else                 { A = g_v2n; B = g_p1n; diag = g_diag2; cnt = g_cnt2; }

    __shared__ __align__(16) float As[8][132];   // pad 4 -> conflict-free stores
    __shared__ __align__(16) float Bs[8][132];
    __shared__ int scnt[128];

    int tid = threadIdx.x;
    int row0 = blockIdx.y * 128;
    int col0 = blockIdx.x * 128;

    if (tid < 128) scnt[tid] = 0;

    int m  = tid >> 1;            // 0..127
    int kq = (tid & 1) * 4;       // 0 or 4
    const float* gA = A + (long)(row0 + m) * C + kq;
    const float* gB = B + (long)(col0 + m) * C + kq;

    int ty = tid >> 4, tx = tid & 15;
    int rowB = ty * 8, colB = tx * 8;

    float acc[8][8];
    #pragma unroll
    for (int r = 0; r < 8; r++)
        #pragma unroll
        for (int c = 0; c < 8; c++) acc[r][c] = 0.0f;

    float4 ra = *(const float4*)gA;
    float4 rb = *(const float4*)gB;

    #pragma unroll 1
    for (int kt = 0; kt < 32; kt++) {
        As[kq + 0][m] = ra.x; As[kq + 1][m] = ra.y;
        As[kq + 2][m] = ra.z; As[kq + 3][m] = ra.w;
        Bs[kq + 0][m] = rb.x; Bs[kq + 1][m] = rb.y;
        Bs[kq + 2][m] = rb.z; Bs[kq + 3][m] = rb.w;
        __syncthreads();

        if (kt < 31) {
            ra = *(const float4*)(gA + (kt + 1) * 8);
            rb = *(const float4*)(gB + (kt + 1) * 8);
        }

        #pragma unroll
        for (int k = 0; k < 8; k++) {
            float4 a0 = *(const float4*)&As[k][rowB];
            float4 a1 = *(const float4*)&As[k][rowB + 4];
            float4 b0 = *(const float4*)&Bs[k][colB];
            float4 b1 = *(const float4*)&Bs[k][colB + 4];
            float av[8] = {a0.x, a0.y, a0.z, a0.w, a1.x, a1.y, a1.z, a1.w};
            float bv[8] = {b0.x, b0.y, b0.z, b0.w, b1.x, b1.y, b1.z, b1.w};
            #pragma unroll
            for (int r = 0; r < 8; r++)
                #pragma unroll
                for (int c = 0; c < 8; c++)
                    acc[r][c] = fmaf(av[r], bv[c], acc[r][c]);
        }
        __syncthreads();
    }

    // Epilogue: count strictly-greater-than-diagonal (exclude j == i).
    #pragma unroll
    for (int r = 0; r < 8; r++) {
        int grow = row0 + rowB + r;
        float dv = __ldg(&diag[grow]);
        int c8 = 0;
        #pragma unroll
        for (int c = 0; c < 8; c++) {
            int gcol = col0 + colB + c;
            c8 += (acc[r][c] > dv && gcol != grow) ? 1 : 0;
        }
        if (c8) atomicAdd(&scnt[rowB + r], c8);
    }
    __syncthreads();
    if (tid < 128) {
        int v = scnt[tid];
        if (v) atomicAdd(&cnt[row0 + tid], v);
    }
}

// ---------------- kernel 3: final scalars ------------------------------------
__global__ __launch_bounds__(256) void finalize_kernel(float* __restrict__ out)
{
    int tid = threadIdx.x;
    double sd = 0.0, spos = 0.0;
    int r1 = 0, r5 = 0, r10 = 0;
    for (int i = tid; i < N; i += 256) {
        sd += (double)g_diag1[i] + (double)g_diag2[i];
        int c1 = g_cnt1[i], c2 = g_cnt2[i];
        spos += (double)(c1 + c2);
        r1  += (c1 < 1)  + (c2 < 1);
        r5  += (c1 < 5)  + (c2 < 5);
        r10 += (c1 < 10) + (c2 < 10);
    }
    // warp + block reduce
    #pragma unroll
    for (int o = 16; o; o >>= 1) {
        sd   += __shfl_xor_sync(0xffffffffu, sd, o);
        spos += __shfl_xor_sync(0xffffffffu, spos, o);
        r1   += __shfl_xor_sync(0xffffffffu, r1, o);
        r5   += __shfl_xor_sync(0xffffffffu, r5, o);
        r10  += __shfl_xor_sync(0xffffffffu, r10, o);
    }
    __shared__ double s_sd[8], s_sp[8];
    __shared__ int s_r1[8], s_r5[8], s_r10[8];
    int lane = tid & 31, w = tid >> 5;
    if (lane == 0) { s_sd[w] = sd; s_sp[w] = spos; s_r1[w] = r1; s_r5[w] = r5; s_r10[w] = r10; }
    __syncthreads();
    if (tid == 0) {
        double tsd = 0, tsp = 0; int t1 = 0, t5 = 0, t10 = 0;
        for (int i = 0; i < 8; i++) {
            tsd += s_sd[i]; tsp += s_sp[i];
            t1 += s_r1[i]; t5 += s_r5[i]; t10 += s_r10[i];
        }
        double inv2N = 1.0 / (2.0 * (double)N);
        out[0] = (float)(-tsd * inv2N);                 // neg_sim_loss
        out[1] = (float)((double)t1  * inv2N);          // recall@1
        out[2] = (float)((double)t5  * inv2N);          // recall@5
        out[3] = (float)((double)t10 * inv2N);          // recall@10
        out[4] = (float)((tsp + (double)N) * inv2N);    // mean_rk
    }
}

// ---------------- launch ------------------------------------------------------
extern "C" void kernel_launch(void* const* d_in, const int* in_sizes, int n_in,
                              void* d_out, int out_size)
{
    const float* v1 = (const float*)d_in[0];
    const float* v2 = (const float*)d_in[1];
    const float* p1 = (const float*)d_in[2];
    const float* p2 = (const float*)d_in[3];
    float* out = (float*)d_out;

    normalize_kernel<<<N, 256>>>(v1, v2, p1, p2);
    dim3 grid(N / 128, N / 128, 2);
    count_kernel<<<grid, 256>>>();
    finalize_kernel<<<1, 256>>>(out);
}

// round 3
// speedup vs baseline: 2.7467x; 2.7467x over previous
#include <cuda_runtime.h>
#include <cuda_fp16.h>
#include <math.h>
#include <stdint.h>

#define N 8192
#define C 256
#define KE 768            // expanded K: A=[hi|hi|lo], B=[hi|lo|hi] (fp16)
#define TM 256            // CTA M tile
#define TN 128            // CTA N tile
#define KC 64             // K chunk (64 halves = 128B rows)
#define NCHUNK (KE / KC)  // 12
#define NTHREADS 512
#define STAGE_BYTES 49152 // A 32KB + B 16KB

// ---------------- scratch (device globals; no allocation allowed) -----------
__device__ __half g_v1e[(size_t)N * KE];
__device__ __half g_v2e[(size_t)N * KE];
__device__ __half g_p1e[(size_t)N * KE];
__device__ __half g_p2e[(size_t)N * KE];
__device__ float g_diag1[N];
__device__ float g_diag2[N];
__device__ int   g_cnt1[N];
__device__ int   g_cnt2[N];

// ---------------- helpers ----------------------------------------------------
__device__ __forceinline__ uint32_t smem_u32(const void* p) {
    uint32_t a;
    asm("{ .reg .u64 t; cvta.to.shared.u64 t, %1; cvt.u32.u64 %0, t; }" : "=r"(a) : "l"(p));
    return a;
}
#define SWZ(x) ((x) ^ (((x) >> 3) & 0x70))

__device__ __forceinline__ void cp_async16(uint32_t sa, const void* g) {
    asm volatile("cp.async.cg.shared.global [%0], [%1], 16;" :: "r"(sa), "l"(g));
}
__device__ __forceinline__ void ldsm_x4(uint32_t* r, uint32_t addr) {
    asm volatile("ldmatrix.sync.aligned.m8n8.x4.shared.b16 {%0,%1,%2,%3}, [%4];"
                 : "=r"(r[0]), "=r"(r[1]), "=r"(r[2]), "=r"(r[3]) : "r"(addr));
}
__device__ __forceinline__ void mma16816(float* d, const uint32_t* a, const uint32_t* b) {
    asm volatile("mma.sync.aligned.m16n8k16.row.col.f32.f16.f16.f32 "
                 "{%0,%1,%2,%3}, {%4,%5,%6,%7}, {%8,%9}, {%0,%1,%2,%3};"
                 : "+f"(d[0]), "+f"(d[1]), "+f"(d[2]), "+f"(d[3])
                 : "r"(a[0]), "r"(a[1]), "r"(a[2]), "r"(a[3]), "r"(b[0]), "r"(b[1]));
}

// ---------------- block reduce (256 threads) --------------------------------
__device__ __forceinline__ float blockReduceSum256(float v, float* sred) {
    #pragma unroll
    for (int o = 16; o; o >>= 1) v += __shfl_xor_sync(0xffffffffu, v, o);
    int lane = threadIdx.x & 31, w = threadIdx.x >> 5;
    if (lane == 0) sred[w] = v;
    __syncthreads();
    if (w == 0) {
        v = (lane < 8) ? sred[lane] : 0.0f;
        #pragma unroll
        for (int o = 4; o; o >>= 1) v += __shfl_xor_sync(0xffffffffu, v, o);
        if (lane == 0) sred[0] = v;
    }
    __syncthreads();
    float r = sred[0];
    __syncthreads();
    return r;
}

// ---------------- kernel 1: normalize + fp16 hi/lo split + diagonal dots ----
__global__ __launch_bounds__(256) void normalize_kernel(
    const float* __restrict__ v1, const float* __restrict__ v2,
    const float* __restrict__ p1, const float* __restrict__ p2)
{
    __shared__ float sred[8];
    int row = blockIdx.x;
    int t = threadIdx.x;
    size_t off = (size_t)row * C + t;

    float a = v1[off], b = v2[off], c = p1[off], d = p2[off];

    float na = blockReduceSum256(a * a, sred);
    float nb = blockReduceSum256(b * b, sred);
    float nc = blockReduceSum256(c * c, sred);
    float nd = blockReduceSum256(d * d, sred);

    float ia = 1.0f / fmaxf(sqrtf(na), 1e-12f);
    float ib = 1.0f / fmaxf(sqrtf(nb), 1e-12f);
    float ic = 1.0f / fmaxf(sqrtf(nc), 1e-12f);
    float id = 1.0f / fmaxf(sqrtf(nd), 1e-12f);

    float an = a * ia, bn = b * ib, cn = c * ic, dn = d * id;

    size_t eb = (size_t)row * KE + t;
    // v-role (A): [hi | hi | lo]
    {
        __half h = __float2half_rn(an);
        __half l = __float2half_rn(an - __half2float(h));
        g_v1e[eb] = h; g_v1e[eb + 256] = h; g_v1e[eb + 512] = l;
        h = __float2half_rn(bn);
        l = __float2half_rn(bn - __half2float(h));
        g_v2e[eb] = h; g_v2e[eb + 256] = h; g_v2e[eb + 512] = l;
    }
    // p-role (B): [hi | lo | hi]
    {
        __half h = __float2half_rn(cn);
        __half l = __float2half_rn(cn - __half2float(h));
        g_p1e[eb] = h; g_p1e[eb + 256] = l; g_p1e[eb + 512] = h;
        h = __float2half_rn(dn);
        l = __float2half_rn(dn - __half2float(h));
        g_p2e[eb] = h; g_p2e[eb + 256] = l; g_p2e[eb + 512] = h;
    }

    float d1 = blockReduceSum256(an * dn, sred);   // v1n . p2n
    float d2 = blockReduceSum256(bn * cn, sred);   // v2n . p1n

    if (t == 0) {
        g_diag1[row] = d1;
        g_diag2[row] = d2;
        g_cnt1[row] = 0;
        g_cnt2[row] = 0;
    }
}

// ---------------- kernel 2: mma.sync GEMM + greater-than-diagonal count -----
// CTA: 256x128 tile, 512 threads (16 warps, 4M x 4N), warp tile 64x32.
// K=768 in 12 chunks of 64 halves; cp.async double buffer.
extern __shared__ char dynsmem[];

__global__ void __launch_bounds__(NTHREADS, 1) count_kernel()
{
    __shared__ int scnt[TM];

    const __half* __restrict__ A;
    const __half* __restrict__ B;
    const float* __restrict__ diag;
    int* cnt;
    if (blockIdx.z == 0) { A = g_v1e; B = g_p2e; diag = g_diag1; cnt = g_cnt1; }
    else                 { A = g_v2e; B = g_p1e; diag = g_diag2; cnt = g_cnt2; }

    int tid = threadIdx.x;
    int wid = tid >> 5;
    int lane = tid & 31;
    int wm = wid >> 2;            // 0..3
    int wn = wid & 3;             // 0..3
    int row0 = blockIdx.y * TM;
    int col0 = blockIdx.x * TN;

    char* al = (char*)((((uintptr_t)dynsmem) + 1023) & ~(uintptr_t)1023);
    uint32_t sbase = smem_u32(al);

    if (tid < TM) scnt[tid] = 0;

    // ---- async chunk loader (A: 256x128B, B: 128x128B, swizzled) ----
    auto load_chunk = [&](int c, int s) {
        uint32_t st = sbase + (uint32_t)s * STAGE_BYTES;
        #pragma unroll
        for (int i = 0; i < 4; i++) {            // A: 2048 x 16B
            int idx = tid + i * NTHREADS;
            int r = idx >> 3, kg = idx & 7;
            const __half* g = A + (size_t)(row0 + r) * KE + c * KC + kg * 8;
            cp_async16(st + SWZ((uint32_t)(r * 128 + kg * 16)), g);
        }
        #pragma unroll
        for (int i = 0; i < 2; i++) {            // B: 1024 x 16B
            int idx = tid + i * NTHREADS;
            int r = idx >> 3, kg = idx & 7;
            const __half* g = B + (size_t)(col0 + r) * KE + c * KC + kg * 8;
            cp_async16(st + 32768u + SWZ((uint32_t)(r * 128 + kg * 16)), g);
        }
        asm volatile("cp.async.commit_group;" ::: "memory");
    };

    float acc[4][4][4];
    #pragma unroll
    for (int mi = 0; mi < 4; mi++)
        #pragma unroll
        for (int n8 = 0; n8 < 4; n8++)
            #pragma unroll
            for (int e = 0; e < 4; e++) acc[mi][n8][e] = 0.0f;

    load_chunk(0, 0);

    for (int c = 0; c < NCHUNK; c++) {
        if (c + 1 < NCHUNK) {
            load_chunk(c + 1, (c + 1) & 1);
            asm volatile("cp.async.wait_group 1;" ::: "memory");
        } else {
            asm volatile("cp.async.wait_group 0;" ::: "memory");
        }
        __syncthreads();

        uint32_t stA = sbase + (uint32_t)(c & 1) * STAGE_BYTES;
        uint32_t stB = stA + 32768u;

        #pragma unroll
        for (int ks = 0; ks < 4; ks++) {         // k16 steps within chunk
            uint32_t a[4][4], b[2][4];
            int kbA = ks * 32 + (lane >> 4) * 16;
            #pragma unroll
            for (int mi = 0; mi < 4; mi++) {
                int rowA = wm * 64 + mi * 16 + (lane & 15);
                uint32_t ad = stA + (uint32_t)(rowA * 128) +
                              (uint32_t)(kbA ^ ((rowA & 7) << 4));
                ldsm_x4(a[mi], ad);
            }
            int kbB = ks * 32 + ((lane >> 3) & 1) * 16;
            #pragma unroll
            for (int nb = 0; nb < 2; nb++) {
                int rowB = wn * 32 + nb * 16 + (lane & 7) + ((lane >> 4) & 1) * 8;
                uint32_t bd = stB + (uint32_t)(rowB * 128) +
                              (uint32_t)(kbB ^ ((rowB & 7) << 4));
                ldsm_x4(b[nb], bd);
            }
            #pragma unroll
            for (int mi = 0; mi < 4; mi++)
                #pragma unroll
                for (int n8 = 0; n8 < 4; n8++)
                    mma16816(acc[mi][n8], a[mi], &b[n8 >> 1][(n8 & 1) * 2]);
        }
        __syncthreads();
    }

    // ---- epilogue: count strictly-greater-than-diagonal --------------------
    int gid = lane >> 2, tig = lane & 3;
    #pragma unroll
    for (int mi = 0; mi < 4; mi++) {
        #pragma unroll
        for (int h = 0; h < 2; h++) {
            int lrow = wm * 64 + mi * 16 + gid + h * 8;
            int grow = row0 + lrow;
            float dv = __ldg(&diag[grow]);
            int cc = 0;
            #pragma unroll
            for (int n8 = 0; n8 < 4; n8++) {
                #pragma unroll
                for (int e = 0; e < 2; e++) {
                    float vv = acc[mi][n8][h * 2 + e];
                    int gcol = col0 + wn * 32 + n8 * 8 + tig * 2 + e;
                    cc += (vv > dv && gcol != grow) ? 1 : 0;
                }
            }
            if (cc) atomicAdd(&scnt[lrow], cc);
        }
    }
    __syncthreads();
    if (tid < TM) {
        int v = scnt[tid];
        if (v) atomicAdd(&cnt[row0 + tid], v);
    }
}

// ---------------- kernel 3: final scalars ------------------------------------
__global__ __launch_bounds__(256) void finalize_kernel(float* __restrict__ out)
{
    int tid = threadIdx.x;
    double sd = 0.0, spos = 0.0;
    int r1 = 0, r5 = 0, r10 = 0;
    for (int i = tid; i < N; i += 256) {
        sd += (double)g_diag1[i] + (double)g_diag2[i];
        int c1 = g_cnt1[i], c2 = g_cnt2[i];
        spos += (double)(c1 + c2);
        r1  += (c1 < 1)  + (c2 < 1);
        r5  += (c1 < 5)  + (c2 < 5);
        r10 += (c1 < 10) + (c2 < 10);
    }
    #pragma unroll
    for (int o = 16; o; o >>= 1) {
        sd   += __shfl_xor_sync(0xffffffffu, sd, o);
        spos += __shfl_xor_sync(0xffffffffu, spos, o);
        r1   += __shfl_xor_sync(0xffffffffu, r1, o);
        r5   += __shfl_xor_sync(0xffffffffu, r5, o);
        r10  += __shfl_xor_sync(0xffffffffu, r10, o);
    }
    __shared__ double s_sd[8], s_sp[8];
    __shared__ int s_r1[8], s_r5[8], s_r10[8];
    int lane = tid & 31, w = tid >> 5;
    if (lane == 0) { s_sd[w] = sd; s_sp[w] = spos; s_r1[w] = r1; s_r5[w] = r5; s_r10[w] = r10; }
    __syncthreads();
    if (tid == 0) {
        double tsd = 0, tsp = 0; int t1 = 0, t5 = 0, t10 = 0;
        for (int i = 0; i < 8; i++) {
            tsd += s_sd[i]; tsp += s_sp[i];
            t1 += s_r1[i]; t5 += s_r5[i]; t10 += s_r10[i];
        }
        double inv2N = 1.0 / (2.0 * (double)N);
        out[0] = (float)(-tsd * inv2N);
        out[1] = (float)((double)t1  * inv2N);
        out[2] = (float)((double)t5  * inv2N);
        out[3] = (float)((double)t10 * inv2N);
        out[4] = (float)((tsp + (double)N) * inv2N);
    }
}

// ---------------- launch ------------------------------------------------------
extern "C" void kernel_launch(void* const* d_in, const int* in_sizes, int n_in,
                              void* d_out, int out_size)
{
    const float* v1 = (const float*)d_in[0];
    const float* v2 = (const float*)d_in[1];
    const float* p1 = (const float*)d_in[2];
    const float* p2 = (const float*)d_in[3];
    float* out = (float*)d_out;

    static const int SMEM_BYTES = 2 * STAGE_BYTES + 1024;
    cudaFuncSetAttribute(count_kernel, cudaFuncAttributeMaxDynamicSharedMemorySize, SMEM_BYTES);

    normalize_kernel<<<N, 256>>>(v1, v2, p1, p2);
    dim3 grid(N / TN, N / TM, 2);
    count_kernel<<<grid, NTHREADS, SMEM_BYTES>>>();
    finalize_kernel<<<1, 256>>>(out);
}